// round 2
// baseline (speedup 1.0000x reference)
#include <cuda_runtime.h>

#define NN 100000
#define NE 600000
#define DD 128
#define LL 4
#define BM 128
#define BK 16
#define MB ((NN + BM - 1) / BM)

// Scratch (allocation-free rule: __device__ globals). 16B-aligned for float4 /
// red.global.add.v4.f32 access.
__device__ __align__(16) float g_agg[NN * DD];
__device__ __align__(16) float g_z[NN * DD];
__device__ __align__(16) float g_h[NN * DD];
__device__ __align__(16) float g_sum[DD];
__device__ __align__(16) float g_sumsq[DD];
__device__ __align__(16) float g_scale[DD];
__device__ __align__(16) float g_shift[DD];
__device__ int g_src[NE];
__device__ int g_dst[NE];
__device__ int g_is64;

// ---------------------------------------------------------------------------
// Edge-index dtype detection + conversion.
// If the harness passes int64 (values < 2^17), every odd 32-bit word of the
// first 64 words is zero. With int32 random indices in [0,1e5) the chance of
// that is ~(1e-5)^32 ~ 0. Deterministic: same input -> same result.
// ---------------------------------------------------------------------------
__global__ void detect_kernel(const int* __restrict__ ei32) {
    int all0 = 1;
#pragma unroll
    for (int i = 1; i < 64; i += 2) all0 &= (ei32[i] == 0);
    g_is64 = all0;
}

__global__ void convert_kernel(const void* __restrict__ ei) {
    int e = blockIdx.x * blockDim.x + threadIdx.x;
    if (e >= NE) return;
    if (g_is64) {
        const long long* p = (const long long*)ei;
        g_src[e] = (int)p[e];
        g_dst[e] = (int)p[NE + e];
    } else {
        const int* p = (const int*)ei;
        g_src[e] = p[e];
        g_dst[e] = p[NE + e];
    }
}

// ---------------------------------------------------------------------------
// agg = (1+eps)*h  (also zeroes the BN stat accumulators)
// ---------------------------------------------------------------------------
__global__ void init_kernel(const float* __restrict__ h,
                            const float* __restrict__ eps_l) {
    int i = blockIdx.x * blockDim.x + threadIdx.x;
    if (i < DD) { g_sum[i] = 0.f; g_sumsq[i] = 0.f; }
    float s = 1.0f + __ldg(eps_l);
    float4 v = ((const float4*)h)[i];
    v.x *= s; v.y *= s; v.z *= s; v.w *= s;
    ((float4*)g_agg)[i] = v;
}

// ---------------------------------------------------------------------------
// Edge phase: one warp per edge. Each lane handles 4 features (float4).
// m = relu(h[src] + a*We + be);  agg[dst] += m  via red.global.add.v4.f32
// ---------------------------------------------------------------------------
__global__ void __launch_bounds__(256) scatter_kernel(
    const float* __restrict__ h,
    const float* __restrict__ ea,
    const float* __restrict__ We_l,
    const float* __restrict__ be_l) {
    int e = (blockIdx.x * 256 + threadIdx.x) >> 5;
    if (e >= NE) return;
    int lane = threadIdx.x & 31;
    int src = g_src[e];
    int dst = g_dst[e];
    float a = __ldg(&ea[e]);
    float4 w  = ((const float4*)We_l)[lane];
    float4 bb = ((const float4*)be_l)[lane];
    float4 hv = ((const float4*)h)[src * 32 + lane];
    float4 m;
    m.x = fmaxf(hv.x + fmaf(a, w.x, bb.x), 0.f);
    m.y = fmaxf(hv.y + fmaf(a, w.y, bb.y), 0.f);
    m.z = fmaxf(hv.z + fmaf(a, w.z, bb.z), 0.f);
    m.w = fmaxf(hv.w + fmaf(a, w.w, bb.w), 0.f);
    float* p = &g_agg[dst * DD + lane * 4];
    asm volatile("red.global.add.v4.f32 [%0], {%1,%2,%3,%4};"
                 :: "l"(p), "f"(m.x), "f"(m.y), "f"(m.z), "f"(m.w)
                 : "memory");
}

// ---------------------------------------------------------------------------
// GEMM1: z = agg @ W1 + b1, fused per-column sum/sumsq accumulation
// 128x128 block tile, 256 threads, 8x8 register blocking, BK=16
// ---------------------------------------------------------------------------
__global__ void __launch_bounds__(256) gemm1_kernel(
    const float* __restrict__ W,
    const float* __restrict__ bias) {
    __shared__ float As[BM * BK];
    __shared__ float Ws[BK * DD];
    const float* A = g_agg;
    int tid = threadIdx.x;
    int tx = tid & 15, ty = tid >> 4;
    int row0 = blockIdx.x * BM;
    float acc[8][8];
#pragma unroll
    for (int i = 0; i < 8; i++)
#pragma unroll
        for (int j = 0; j < 8; j++) acc[i][j] = 0.f;

    for (int k0 = 0; k0 < DD; k0 += BK) {
#pragma unroll
        for (int t = 0; t < 2; t++) {
            int idx = tid + t * 256;
            int r = idx >> 2, c4 = (idx & 3) * 4;
            int row = row0 + r;
            float4 v = make_float4(0.f, 0.f, 0.f, 0.f);
            if (row < NN) v = *(const float4*)&A[row * DD + k0 + c4];
            *(float4*)&As[r * BK + c4] = v;
        }
#pragma unroll
        for (int t = 0; t < 2; t++) {
            int idx = tid + t * 256;
            int r = idx >> 5, c4 = (idx & 31) * 4;
            *(float4*)&Ws[r * DD + c4] = *(const float4*)&W[(k0 + r) * DD + c4];
        }
        __syncthreads();
#pragma unroll
        for (int kk = 0; kk < BK; kk++) {
            float a[8], b[8];
#pragma unroll
            for (int i = 0; i < 8; i++) a[i] = As[(ty * 8 + i) * BK + kk];
            float4 b0 = *(const float4*)&Ws[kk * DD + tx * 8];
            float4 b1v = *(const float4*)&Ws[kk * DD + tx * 8 + 4];
            b[0] = b0.x; b[1] = b0.y; b[2] = b0.z; b[3] = b0.w;
            b[4] = b1v.x; b[5] = b1v.y; b[6] = b1v.z; b[7] = b1v.w;
#pragma unroll
            for (int i = 0; i < 8; i++)
#pragma unroll
                for (int j = 0; j < 8; j++)
                    acc[i][j] = fmaf(a[i], b[j], acc[i][j]);
        }
        __syncthreads();
    }

    float4 bi0 = *(const float4*)&bias[tx * 8];
    float4 bi1 = *(const float4*)&bias[tx * 8 + 4];
    float bb[8] = {bi0.x, bi0.y, bi0.z, bi0.w, bi1.x, bi1.y, bi1.z, bi1.w};
    float psum[8], psq[8];
#pragma unroll
    for (int j = 0; j < 8; j++) { psum[j] = 0.f; psq[j] = 0.f; }
#pragma unroll
    for (int i = 0; i < 8; i++) {
        int row = row0 + ty * 8 + i;
        if (row < NN) {
            float v[8];
#pragma unroll
            for (int j = 0; j < 8; j++) {
                v[j] = acc[i][j] + bb[j];
                psum[j] += v[j];
                psq[j] += v[j] * v[j];
            }
            *(float4*)&g_z[row * DD + tx * 8]     = make_float4(v[0], v[1], v[2], v[3]);
            *(float4*)&g_z[row * DD + tx * 8 + 4] = make_float4(v[4], v[5], v[6], v[7]);
        }
    }
    // block-level reduction of stats into smem (reuse Ws), then global atomics
    float* rsum = Ws;
    float* rsq = Ws + DD;
    __syncthreads();
    if (tid < DD) { rsum[tid] = 0.f; rsq[tid] = 0.f; }
    __syncthreads();
#pragma unroll
    for (int j = 0; j < 8; j++) {
        atomicAdd(&rsum[tx * 8 + j], psum[j]);
        atomicAdd(&rsq[tx * 8 + j], psq[j]);
    }
    __syncthreads();
    if (tid < DD) {
        atomicAdd(&g_sum[tid], rsum[tid]);
        atomicAdd(&g_sumsq[tid], rsq[tid]);
    }
}

// ---------------------------------------------------------------------------
// Fold BN stats into per-feature scale/shift: y = relu(z*scale + shift)
// ---------------------------------------------------------------------------
__global__ void finalize_kernel(const float* __restrict__ gamma,
                                const float* __restrict__ beta) {
    int t = threadIdx.x;
    if (t < DD) {
        float mu = g_sum[t] * (1.0f / NN);
        float var = g_sumsq[t] * (1.0f / NN) - mu * mu;
        float rs = rsqrtf(var + 1e-5f);
        float sc = rs * gamma[t];
        g_scale[t] = sc;
        g_shift[t] = beta[t] - mu * sc;
    }
}

// ---------------------------------------------------------------------------
// GEMM2: out = (l? h_in : 0) + relu( relu(BN(z)) @ W2 + b2 )
// BN+relu applied while loading the A tile; bias+relu+residual in epilogue
// ---------------------------------------------------------------------------
__global__ void __launch_bounds__(256) gemm2_kernel(
    const float* __restrict__ W,
    const float* __restrict__ bias,
    const float* __restrict__ h_res,
    float* __restrict__ out,
    int add_res) {
    __shared__ float As[BM * BK];
    __shared__ float Ws[BK * DD];
    int tid = threadIdx.x;
    int tx = tid & 15, ty = tid >> 4;
    int row0 = blockIdx.x * BM;
    float acc[8][8];
#pragma unroll
    for (int i = 0; i < 8; i++)
#pragma unroll
        for (int j = 0; j < 8; j++) acc[i][j] = 0.f;

    for (int k0 = 0; k0 < DD; k0 += BK) {
#pragma unroll
        for (int t = 0; t < 2; t++) {
            int idx = tid + t * 256;
            int r = idx >> 2, c4 = (idx & 3) * 4;
            int row = row0 + r;
            float4 v = make_float4(0.f, 0.f, 0.f, 0.f);
            if (row < NN) {
                float4 z = *(const float4*)&g_z[row * DD + k0 + c4];
                float4 sc = *(const float4*)&g_scale[k0 + c4];
                float4 sh = *(const float4*)&g_shift[k0 + c4];
                v.x = fmaxf(fmaf(z.x, sc.x, sh.x), 0.f);
                v.y = fmaxf(fmaf(z.y, sc.y, sh.y), 0.f);
                v.z = fmaxf(fmaf(z.z, sc.z, sh.z), 0.f);
                v.w = fmaxf(fmaf(z.w, sc.w, sh.w), 0.f);
            }
            *(float4*)&As[r * BK + c4] = v;
        }
#pragma unroll
        for (int t = 0; t < 2; t++) {
            int idx = tid + t * 256;
            int r = idx >> 5, c4 = (idx & 31) * 4;
            *(float4*)&Ws[r * DD + c4] = *(const float4*)&W[(k0 + r) * DD + c4];
        }
        __syncthreads();
#pragma unroll
        for (int kk = 0; kk < BK; kk++) {
            float a[8], b[8];
#pragma unroll
            for (int i = 0; i < 8; i++) a[i] = As[(ty * 8 + i) * BK + kk];
            float4 b0 = *(const float4*)&Ws[kk * DD + tx * 8];
            float4 b1v = *(const float4*)&Ws[kk * DD + tx * 8 + 4];
            b[0] = b0.x; b[1] = b0.y; b[2] = b0.z; b[3] = b0.w;
            b[4] = b1v.x; b[5] = b1v.y; b[6] = b1v.z; b[7] = b1v.w;
#pragma unroll
            for (int i = 0; i < 8; i++)
#pragma unroll
                for (int j = 0; j < 8; j++)
                    acc[i][j] = fmaf(a[i], b[j], acc[i][j]);
        }
        __syncthreads();
    }

    float4 bi0 = *(const float4*)&bias[tx * 8];
    float4 bi1 = *(const float4*)&bias[tx * 8 + 4];
    float bb[8] = {bi0.x, bi0.y, bi0.z, bi0.w, bi1.x, bi1.y, bi1.z, bi1.w};
#pragma unroll
    for (int i = 0; i < 8; i++) {
        int row = row0 + ty * 8 + i;
        if (row < NN) {
            float v[8];
#pragma unroll
            for (int j = 0; j < 8; j++)
                v[j] = fmaxf(acc[i][j] + bb[j], 0.f);
            if (add_res) {
                float4 r0 = *(const float4*)&h_res[row * DD + tx * 8];
                float4 r1 = *(const float4*)&h_res[row * DD + tx * 8 + 4];
                v[0] += r0.x; v[1] += r0.y; v[2] += r0.z; v[3] += r0.w;
                v[4] += r1.x; v[5] += r1.y; v[6] += r1.z; v[7] += r1.w;
            }
            *(float4*)&out[row * DD + tx * 8]     = make_float4(v[0], v[1], v[2], v[3]);
            *(float4*)&out[row * DD + tx * 8 + 4] = make_float4(v[4], v[5], v[6], v[7]);
        }
    }
}

// ---------------------------------------------------------------------------
extern "C" void kernel_launch(void* const* d_in, const int* in_sizes, int n_in,
                              void* d_out, int out_size) {
    const float* x     = (const float*)d_in[0];
    const void*  ei    = d_in[1];
    const float* ea    = (const float*)d_in[2];
    const float* We    = (const float*)d_in[3];
    const float* be    = (const float*)d_in[4];
    const float* eps   = (const float*)d_in[5];
    const float* W1    = (const float*)d_in[6];
    const float* b1    = (const float*)d_in[7];
    const float* gamma = (const float*)d_in[8];
    const float* beta  = (const float*)d_in[9];
    const float* W2    = (const float*)d_in[10];
    const float* b2    = (const float*)d_in[11];

    void* hp;
    cudaGetSymbolAddress(&hp, g_h);
    float* gh = (float*)hp;

    detect_kernel<<<1, 1>>>((const int*)ei);
    convert_kernel<<<(NE + 255) / 256, 256>>>(ei);

    for (int l = 0; l < LL; l++) {
        const float* h_in = (l == 0) ? x : gh;
        float* h_out = (l == LL - 1) ? (float*)d_out : gh;
        init_kernel<<<(NN * DD / 4) / 256, 256>>>(h_in, eps + l);
        scatter_kernel<<<NE / 8, 256>>>(h_in, ea, We + l * DD, be + l * DD);
        gemm1_kernel<<<MB, 256>>>(W1 + l * DD * DD, b1 + l * DD);
        finalize_kernel<<<1, 128>>>(gamma + l * DD, beta + l * DD);
        gemm2_kernel<<<MB, 256>>>(W2 + l * DD * DD, b2 + l * DD, h_in, h_out,
                                  l > 0 ? 1 : 0);
    }
}

// round 4
// speedup vs baseline: 1.7739x; 1.7739x over previous
#include <cuda_runtime.h>

#define NN 100000
#define NE 600000
#define DD 128
#define LL 4
#define BM 128
#define MB ((NN + BM - 1) / BM)

#define W_PAD 136   // 128 + 8 : conflict-free B-fragment LDS
#define A_PAD 36    // 32 + 4  : conflict-free A-fragment LDS
#define GSMEM ((128 * W_PAD + 128 * A_PAD) * 4)

// Scratch (allocation-free rule: __device__ globals)
__device__ __align__(16) float g_agg[NN * DD];
__device__ __align__(16) float g_z[NN * DD];
__device__ __align__(16) float g_h[NN * DD];
__device__ __align__(16) float g_sum[DD];
__device__ __align__(16) float g_sumsq[DD];
__device__ __align__(16) float g_scale[DD];
__device__ __align__(16) float g_shift[DD];
__device__ int g_src[NE];
__device__ int g_dst[NE];
__device__ int g_is64;

// ---------------------------------------------------------------------------
// helpers
// ---------------------------------------------------------------------------
__device__ __forceinline__ unsigned f2tf(float f) {
    unsigned u;
    asm("cvt.rna.tf32.f32 %0, %1;" : "=r"(u) : "f"(f));
    return u;
}

__device__ __forceinline__ void mma8(float* d, unsigned a0, unsigned a1,
                                     unsigned a2, unsigned a3,
                                     unsigned b0, unsigned b1) {
    asm volatile(
        "mma.sync.aligned.m16n8k8.row.col.f32.tf32.tf32.f32 "
        "{%0,%1,%2,%3},{%4,%5,%6,%7},{%8,%9},{%0,%1,%2,%3};"
        : "+f"(d[0]), "+f"(d[1]), "+f"(d[2]), "+f"(d[3])
        : "r"(a0), "r"(a1), "r"(a2), "r"(a3), "r"(b0), "r"(b1));
}

// ---------------------------------------------------------------------------
// Edge-index dtype detection + conversion (indices < 2^17, so int64 layout
// has all-odd-words-zero; false positive prob with int32 ~ (1e-5)^32 ~ 0).
// ---------------------------------------------------------------------------
__global__ void detect_kernel(const int* __restrict__ ei32) {
    int all0 = 1;
#pragma unroll
    for (int i = 1; i < 64; i += 2) all0 &= (ei32[i] == 0);
    g_is64 = all0;
}

__global__ void convert_kernel(const void* __restrict__ ei) {
    int e = blockIdx.x * blockDim.x + threadIdx.x;
    if (e >= NE) return;
    if (g_is64) {
        const long long* p = (const long long*)ei;
        g_src[e] = (int)p[e];
        g_dst[e] = (int)p[NE + e];
    } else {
        const int* p = (const int*)ei;
        g_src[e] = p[e];
        g_dst[e] = p[NE + e];
    }
}

// ---------------------------------------------------------------------------
// zero agg + BN stat accumulators
// ---------------------------------------------------------------------------
__global__ void zero_kernel() {
    int i = blockIdx.x * blockDim.x + threadIdx.x;
    if (i < DD) { g_sum[i] = 0.f; g_sumsq[i] = 0.f; }
    ((float4*)g_agg)[i] = make_float4(0.f, 0.f, 0.f, 0.f);
}

// ---------------------------------------------------------------------------
// Edge phase: one warp per edge, red.global.add.v4.f32 into g_agg
// ---------------------------------------------------------------------------
__global__ void __launch_bounds__(256) scatter_kernel(
    const float* __restrict__ h,
    const float* __restrict__ ea,
    const float* __restrict__ We_l,
    const float* __restrict__ be_l) {
    int e = (blockIdx.x * 256 + threadIdx.x) >> 5;
    if (e >= NE) return;
    int lane = threadIdx.x & 31;
    int src = g_src[e];
    int dst = g_dst[e];
    float a = __ldg(&ea[e]);
    float4 w  = ((const float4*)We_l)[lane];
    float4 bb = ((const float4*)be_l)[lane];
    float4 hv = ((const float4*)h)[src * 32 + lane];
    float4 m;
    m.x = fmaxf(hv.x + fmaf(a, w.x, bb.x), 0.f);
    m.y = fmaxf(hv.y + fmaf(a, w.y, bb.y), 0.f);
    m.z = fmaxf(hv.z + fmaf(a, w.z, bb.z), 0.f);
    m.w = fmaxf(hv.w + fmaf(a, w.w, bb.w), 0.f);
    float* p = &g_agg[dst * DD + lane * 4];
    asm volatile("red.global.add.v4.f32 [%0], {%1,%2,%3,%4};"
                 :: "l"(p), "f"(m.x), "f"(m.y), "f"(m.z), "f"(m.w)
                 : "memory");
}

// ---------------------------------------------------------------------------
// tf32 tensor-core GEMM, 128x128 CTA tile, 8 warps (4M x 2N), warp 32x64.
// MODE 1: z = (agg + (1+eps)*h) @ W + b, fused BN sum/sumsq  -> g_z
// MODE 2: out = [res +] relu( relu(BN(z)) @ W + b )          -> outp
// ---------------------------------------------------------------------------
template <int MODE>
__global__ void __launch_bounds__(256, 2) gemm_tc(
    const float* __restrict__ W,
    const float* __restrict__ bias,
    const float* __restrict__ aux,    // MODE1: h_in ; MODE2: residual
    const float* __restrict__ eps_l,  // MODE1 only
    float* __restrict__ outp,         // MODE2 only
    int add_res) {
    extern __shared__ float sm[];
    float* Ws = sm;                      // [128][W_PAD]
    float* As = sm + 128 * W_PAD;        // [128][A_PAD]
    unsigned* Wu = (unsigned*)Ws;
    unsigned* Au = (unsigned*)As;

    int tid = threadIdx.x;
    int lane = tid & 31, wid = tid >> 5;
    int wm = wid & 3, wn = wid >> 2;     // warp grid 4(M) x 2(N)
    int g = lane >> 2, t = lane & 3;
    int row0 = blockIdx.x * BM;

    // ---- load W into smem as tf32 (whole 128x128) ----
    {
        int r = tid >> 5, c = lane * 4;
#pragma unroll
        for (int p = 0; p < 16; p++) {
            int row = r + p * 8;
            float4 v = *(const float4*)&W[row * DD + c];
            uint4 u = make_uint4(f2tf(v.x), f2tf(v.y), f2tf(v.z), f2tf(v.w));
            *(uint4*)&Wu[row * W_PAD + c] = u;
        }
    }

    float acc[2][8][4];
#pragma unroll
    for (int mi = 0; mi < 2; mi++)
#pragma unroll
        for (int ni = 0; ni < 8; ni++)
#pragma unroll
            for (int q = 0; q < 4; q++) acc[mi][ni][q] = 0.f;

    float s = (MODE == 1) ? (1.0f + __ldg(eps_l)) : 0.f;

    for (int ko = 0; ko < 4; ko++) {
        __syncthreads();
        // ---- load A tile [128 x 32] with fused pre-op ----
        {
            int r = tid >> 3, c = (tid & 7) * 4;
#pragma unroll
            for (int p = 0; p < 4; p++) {
                int rr = r + p * 32;
                int row = row0 + rr;
                float4 v = make_float4(0.f, 0.f, 0.f, 0.f);
                if (row < NN) {
                    int off = row * DD + ko * 32 + c;
                    if (MODE == 1) {
                        float4 a = *(const float4*)&g_agg[off];
                        float4 h = *(const float4*)&aux[off];
                        v.x = fmaf(s, h.x, a.x);
                        v.y = fmaf(s, h.y, a.y);
                        v.z = fmaf(s, h.z, a.z);
                        v.w = fmaf(s, h.w, a.w);
                    } else {
                        float4 z = *(const float4*)&g_z[off];
                        float4 sc = *(const float4*)&g_scale[ko * 32 + c];
                        float4 sh = *(const float4*)&g_shift[ko * 32 + c];
                        v.x = fmaxf(fmaf(z.x, sc.x, sh.x), 0.f);
                        v.y = fmaxf(fmaf(z.y, sc.y, sh.y), 0.f);
                        v.z = fmaxf(fmaf(z.z, sc.z, sh.z), 0.f);
                        v.w = fmaxf(fmaf(z.w, sc.w, sh.w), 0.f);
                    }
                }
                uint4 u = make_uint4(f2tf(v.x), f2tf(v.y), f2tf(v.z), f2tf(v.w));
                *(uint4*)&Au[rr * A_PAD + c] = u;
            }
        }
        __syncthreads();
        // ---- compute: 4 k8 steps ----
#pragma unroll
        for (int kk = 0; kk < 4; kk++) {
            int kb = kk * 8;
            int kw = ko * 32 + kb;
            unsigned b0[8], b1[8];
#pragma unroll
            for (int ni = 0; ni < 8; ni++) {
                int col = wn * 64 + ni * 8 + g;
                b0[ni] = Wu[(kw + t) * W_PAD + col];
                b1[ni] = Wu[(kw + t + 4) * W_PAD + col];
            }
#pragma unroll
            for (int mi = 0; mi < 2; mi++) {
                int rb = wm * 32 + mi * 16;
                unsigned a0 = Au[(rb + g) * A_PAD + kb + t];
                unsigned a1 = Au[(rb + g + 8) * A_PAD + kb + t];
                unsigned a2 = Au[(rb + g) * A_PAD + kb + t + 4];
                unsigned a3 = Au[(rb + g + 8) * A_PAD + kb + t + 4];
#pragma unroll
                for (int ni = 0; ni < 8; ni++)
                    mma8(acc[mi][ni], a0, a1, a2, a3, b0[ni], b1[ni]);
            }
        }
    }

    // ---- epilogue ----
    float bcol[16];
#pragma unroll
    for (int ni = 0; ni < 8; ni++) {
        int col = wn * 64 + ni * 8 + 2 * t;
        bcol[ni * 2]     = __ldg(&bias[col]);
        bcol[ni * 2 + 1] = __ldg(&bias[col + 1]);
    }

    if (MODE == 1) {
        float psum[16], psq[16];
#pragma unroll
        for (int i = 0; i < 16; i++) { psum[i] = 0.f; psq[i] = 0.f; }
#pragma unroll
        for (int mi = 0; mi < 2; mi++) {
            int r1 = row0 + wm * 32 + mi * 16 + g;
            int r2 = r1 + 8;
#pragma unroll
            for (int ni = 0; ni < 8; ni++) {
                int col = wn * 64 + ni * 8 + 2 * t;
                float x0 = acc[mi][ni][0] + bcol[ni * 2];
                float x1 = acc[mi][ni][1] + bcol[ni * 2 + 1];
                float x2 = acc[mi][ni][2] + bcol[ni * 2];
                float x3 = acc[mi][ni][3] + bcol[ni * 2 + 1];
                if (r1 < NN) {
                    *(float2*)&g_z[r1 * DD + col] = make_float2(x0, x1);
                    psum[ni * 2] += x0;     psq[ni * 2] += x0 * x0;
                    psum[ni * 2 + 1] += x1; psq[ni * 2 + 1] += x1 * x1;
                }
                if (r2 < NN) {
                    *(float2*)&g_z[r2 * DD + col] = make_float2(x2, x3);
                    psum[ni * 2] += x2;     psq[ni * 2] += x2 * x2;
                    psum[ni * 2 + 1] += x3; psq[ni * 2 + 1] += x3 * x3;
                }
            }
        }
        // reduce over the 8 lanes sharing each t (stride-4 shfl)
#pragma unroll
        for (int d = 4; d < 32; d <<= 1) {
#pragma unroll
            for (int i = 0; i < 16; i++) {
                psum[i] += __shfl_down_sync(0xFFFFFFFFu, psum[i], d);
                psq[i]  += __shfl_down_sync(0xFFFFFFFFu, psq[i], d);
            }
        }
        __syncthreads();             // done reading As — reuse for reduction
        float* ssum = As;
        float* ssq  = As + DD;
        if (tid < DD) { ssum[tid] = 0.f; ssq[tid] = 0.f; }
        __syncthreads();
        if (lane < 4) {
#pragma unroll
            for (int i = 0; i < 16; i++) {
                int col = wn * 64 + (i >> 1) * 8 + 2 * t + (i & 1);
                atomicAdd(&ssum[col], psum[i]);
                atomicAdd(&ssq[col],  psq[i]);
            }
        }
        __syncthreads();
        if (tid < DD) {
            atomicAdd(&g_sum[tid],   ssum[tid]);
            atomicAdd(&g_sumsq[tid], ssq[tid]);
        }
    } else {
#pragma unroll
        for (int mi = 0; mi < 2; mi++) {
            int r1 = row0 + wm * 32 + mi * 16 + g;
            int r2 = r1 + 8;
#pragma unroll
            for (int ni = 0; ni < 8; ni++) {
                int col = wn * 64 + ni * 8 + 2 * t;
                float x0 = fmaxf(acc[mi][ni][0] + bcol[ni * 2], 0.f);
                float x1 = fmaxf(acc[mi][ni][1] + bcol[ni * 2 + 1], 0.f);
                float x2 = fmaxf(acc[mi][ni][2] + bcol[ni * 2], 0.f);
                float x3 = fmaxf(acc[mi][ni][3] + bcol[ni * 2 + 1], 0.f);
                if (r1 < NN) {
                    if (add_res) {
                        float2 rv = *(const float2*)&aux[r1 * DD + col];
                        x0 += rv.x; x1 += rv.y;
                    }
                    *(float2*)&outp[r1 * DD + col] = make_float2(x0, x1);
                }
                if (r2 < NN) {
                    if (add_res) {
                        float2 rv = *(const float2*)&aux[r2 * DD + col];
                        x2 += rv.x; x3 += rv.y;
                    }
                    *(float2*)&outp[r2 * DD + col] = make_float2(x2, x3);
                }
            }
        }
    }
}

// ---------------------------------------------------------------------------
// Fold BN stats into per-feature scale/shift
// ---------------------------------------------------------------------------
__global__ void finalize_kernel(const float* __restrict__ gamma,
                                const float* __restrict__ beta) {
    int tt = threadIdx.x;
    if (tt < DD) {
        float mu = g_sum[tt] * (1.0f / NN);
        float var = g_sumsq[tt] * (1.0f / NN) - mu * mu;
        float rs = rsqrtf(var + 1e-5f);
        float sc = rs * gamma[tt];
        g_scale[tt] = sc;
        g_shift[tt] = beta[tt] - mu * sc;
    }
}

// ---------------------------------------------------------------------------
extern "C" void kernel_launch(void* const* d_in, const int* in_sizes, int n_in,
                              void* d_out, int out_size) {
    const float* x     = (const float*)d_in[0];
    const void*  ei    = d_in[1];
    const float* ea    = (const float*)d_in[2];
    const float* We    = (const float*)d_in[3];
    const float* be    = (const float*)d_in[4];
    const float* eps   = (const float*)d_in[5];
    const float* W1    = (const float*)d_in[6];
    const float* b1    = (const float*)d_in[7];
    const float* gamma = (const float*)d_in[8];
    const float* beta  = (const float*)d_in[9];
    const float* W2    = (const float*)d_in[10];
    const float* b2    = (const float*)d_in[11];

    void* hp;
    cudaGetSymbolAddress(&hp, g_h);
    float* gh = (float*)hp;

    cudaFuncSetAttribute(gemm_tc<1>, cudaFuncAttributeMaxDynamicSharedMemorySize, GSMEM);
    cudaFuncSetAttribute(gemm_tc<2>, cudaFuncAttributeMaxDynamicSharedMemorySize, GSMEM);

    detect_kernel<<<1, 1>>>((const int*)ei);
    convert_kernel<<<(NE + 255) / 256, 256>>>(ei);

    for (int l = 0; l < LL; l++) {
        const float* h_in = (l == 0) ? x : gh;
        float* h_out = (l == LL - 1) ? (float*)d_out : gh;
        zero_kernel<<<(NN * DD / 4) / 256, 256>>>();
        scatter_kernel<<<NE / 8, 256>>>(h_in, ea, We + l * DD, be + l * DD);
        gemm_tc<1><<<MB, 256, GSMEM>>>(W1 + l * DD * DD, b1 + l * DD,
                                       h_in, eps + l, nullptr, 0);
        finalize_kernel<<<1, 128>>>(gamma + l * DD, beta + l * DD);
        gemm_tc<2><<<MB, 256, GSMEM>>>(W2 + l * DD * DD, b2 + l * DD,
                                       h_in, nullptr, h_out, l > 0 ? 1 : 0);
    }
}

// round 5
// speedup vs baseline: 2.2898x; 1.2909x over previous
#include <cuda_runtime.h>

#define NN 100000
#define NE 600000
#define DD 128
#define LL 4
#define BM 128
#define MB ((NN + BM - 1) / BM)
#define NBLK ((NN + 255) / 256)   // 391 scan blocks

#define W_PAD 136
#define A_PAD 36
#define GSMEM ((128 * W_PAD + 128 * A_PAD) * 4)

// Scratch (allocation-free rule: __device__ globals)
__device__ __align__(16) float g_agg[NN * DD];
__device__ __align__(16) float g_z[NN * DD];
__device__ __align__(16) float g_h[NN * DD];
__device__ __align__(16) float g_sum[DD];
__device__ __align__(16) float g_sumsq[DD];
__device__ __align__(16) float g_scale[DD];
__device__ __align__(16) float g_shift[DD];
__device__ int g_src[NE];
__device__ int g_dst[NE];
__device__ int g_is64;
// CSR
__device__ int g_cnt[NN];
__device__ int g_roff[NN + 1];
__device__ int g_part[NBLK];
__device__ int g_poff[NBLK];
__device__ int g_cursor[NN];
__device__ int g_csr_src[NE];
__device__ __align__(16) float g_csr_a[NE];

// ---------------------------------------------------------------------------
__device__ __forceinline__ unsigned f2tf(float f) {
    unsigned u;
    asm("cvt.rna.tf32.f32 %0, %1;" : "=r"(u) : "f"(f));
    return u;
}

__device__ __forceinline__ void mma8(float* d, unsigned a0, unsigned a1,
                                     unsigned a2, unsigned a3,
                                     unsigned b0, unsigned b1) {
    asm volatile(
        "mma.sync.aligned.m16n8k8.row.col.f32.tf32.tf32.f32 "
        "{%0,%1,%2,%3},{%4,%5,%6,%7},{%8,%9},{%0,%1,%2,%3};"
        : "+f"(d[0]), "+f"(d[1]), "+f"(d[2]), "+f"(d[3])
        : "r"(a0), "r"(a1), "r"(a2), "r"(a3), "r"(b0), "r"(b1));
}

// ---------------------------------------------------------------------------
// Edge-index dtype detection + conversion (indices < 2^17: int64 layout has
// all-odd-words zero; int32 false-positive prob ~ (1e-5)^32 ~ 0).
// ---------------------------------------------------------------------------
__global__ void detect_kernel(const int* __restrict__ ei32) {
    int all0 = 1;
#pragma unroll
    for (int i = 1; i < 64; i += 2) all0 &= (ei32[i] == 0);
    g_is64 = all0;
}

__global__ void convert_kernel(const void* __restrict__ ei) {
    int e = blockIdx.x * blockDim.x + threadIdx.x;
    if (e >= NE) return;
    if (g_is64) {
        const long long* p = (const long long*)ei;
        g_src[e] = (int)p[e];
        g_dst[e] = (int)p[NE + e];
    } else {
        const int* p = (const int*)ei;
        g_src[e] = p[e];
        g_dst[e] = p[NE + e];
    }
}

// ---------------------------------------------------------------------------
// CSR build: histogram -> 2-level exclusive scan -> bucket fill
// ---------------------------------------------------------------------------
__global__ void zcnt_kernel() {
    int i = blockIdx.x * blockDim.x + threadIdx.x;
    if (i < NN) g_cnt[i] = 0;
}

__global__ void hist_kernel() {
    int e = blockIdx.x * blockDim.x + threadIdx.x;
    if (e < NE) atomicAdd(&g_cnt[g_dst[e]], 1);
}

__global__ void scan_block_kernel() {
    __shared__ int sd[256];
    int tid = threadIdx.x;
    int i = blockIdx.x * 256 + tid;
    int v = (i < NN) ? g_cnt[i] : 0;
    sd[tid] = v;
    __syncthreads();
#pragma unroll
    for (int o = 1; o < 256; o <<= 1) {
        int t = (tid >= o) ? sd[tid - o] : 0;
        __syncthreads();
        sd[tid] += t;
        __syncthreads();
    }
    if (i < NN) g_roff[i] = sd[tid] - v;     // exclusive, pre-offset
    if (tid == 255) g_part[blockIdx.x] = sd[255];
}

__global__ void scan_part_kernel() {
    __shared__ int sd[512];
    int tid = threadIdx.x;
    int v = (tid < NBLK) ? g_part[tid] : 0;
    sd[tid] = v;
    __syncthreads();
#pragma unroll
    for (int o = 1; o < 512; o <<= 1) {
        int t = (tid >= o) ? sd[tid - o] : 0;
        __syncthreads();
        sd[tid] += t;
        __syncthreads();
    }
    if (tid < NBLK) g_poff[tid] = sd[tid] - v;
}

__global__ void scan_add_kernel() {
    int i = blockIdx.x * blockDim.x + threadIdx.x;
    if (i < NN) {
        int r = g_roff[i] + g_poff[i >> 8];
        g_roff[i] = r;
        g_cursor[i] = r;
    }
    if (i == 0) g_roff[NN] = NE;
}

__global__ void fill_kernel(const float* __restrict__ ea) {
    int e = blockIdx.x * blockDim.x + threadIdx.x;
    if (e >= NE) return;
    int d = g_dst[e];
    int p = atomicAdd(&g_cursor[d], 1);
    g_csr_src[p] = g_src[e];
    g_csr_a[p] = ea[e];
}

// ---------------------------------------------------------------------------
// Gather-reduce edge phase: one warp per destination node.
// agg[n] = (1+eps)*h[n] + sum_{e: dst=n} relu(h[src_e] + a_e*We + be)
// Also zeroes the BN stat accumulators (block 0).
// ---------------------------------------------------------------------------
__global__ void __launch_bounds__(256) gather_kernel(
    const float* __restrict__ h,
    const float* __restrict__ We_l,
    const float* __restrict__ be_l,
    const float* __restrict__ eps_l) {
    if (blockIdx.x == 0 && threadIdx.x < DD) {
        g_sum[threadIdx.x] = 0.f;
        g_sumsq[threadIdx.x] = 0.f;
    }
    int node = (blockIdx.x * 256 + threadIdx.x) >> 5;
    if (node >= NN) return;
    int lane = threadIdx.x & 31;
    float4 w  = ((const float4*)We_l)[lane];
    float4 bb = ((const float4*)be_l)[lane];
    float s = 1.0f + __ldg(eps_l);
    float4 hv = ((const float4*)h)[node * 32 + lane];
    float4 acc = make_float4(s * hv.x, s * hv.y, s * hv.z, s * hv.w);

    int i = g_roff[node];
    int end = g_roff[node + 1];
    // 2-edge unrolled main loop for memory-level parallelism
    for (; i + 2 <= end; i += 2) {
        int s0 = g_csr_src[i], s1 = g_csr_src[i + 1];
        float a0 = g_csr_a[i], a1 = g_csr_a[i + 1];
        float4 x0 = ((const float4*)h)[s0 * 32 + lane];
        float4 x1 = ((const float4*)h)[s1 * 32 + lane];
        acc.x += fmaxf(x0.x + fmaf(a0, w.x, bb.x), 0.f)
               + fmaxf(x1.x + fmaf(a1, w.x, bb.x), 0.f);
        acc.y += fmaxf(x0.y + fmaf(a0, w.y, bb.y), 0.f)
               + fmaxf(x1.y + fmaf(a1, w.y, bb.y), 0.f);
        acc.z += fmaxf(x0.z + fmaf(a0, w.z, bb.z), 0.f)
               + fmaxf(x1.z + fmaf(a1, w.z, bb.z), 0.f);
        acc.w += fmaxf(x0.w + fmaf(a0, w.w, bb.w), 0.f)
               + fmaxf(x1.w + fmaf(a1, w.w, bb.w), 0.f);
    }
    if (i < end) {
        int s0 = g_csr_src[i];
        float a0 = g_csr_a[i];
        float4 x0 = ((const float4*)h)[s0 * 32 + lane];
        acc.x += fmaxf(x0.x + fmaf(a0, w.x, bb.x), 0.f);
        acc.y += fmaxf(x0.y + fmaf(a0, w.y, bb.y), 0.f);
        acc.z += fmaxf(x0.z + fmaf(a0, w.z, bb.z), 0.f);
        acc.w += fmaxf(x0.w + fmaf(a0, w.w, bb.w), 0.f);
    }
    ((float4*)g_agg)[node * 32 + lane] = acc;
}

// ---------------------------------------------------------------------------
// tf32 tensor-core GEMM, 128x128 CTA tile, 8 warps (4M x 2N), warp 32x64.
// MODE 1: z = agg @ W + b, fused BN sum/sumsq  -> g_z
// MODE 2: out = [res +] relu( relu(BN(z)) @ W + b ) -> outp
// ---------------------------------------------------------------------------
template <int MODE>
__global__ void __launch_bounds__(256, 2) gemm_tc(
    const float* __restrict__ W,
    const float* __restrict__ bias,
    const float* __restrict__ aux,    // MODE2: residual
    float* __restrict__ outp,         // MODE2 only
    int add_res) {
    extern __shared__ float sm[];
    float* Ws = sm;                      // [128][W_PAD]
    float* As = sm + 128 * W_PAD;        // [128][A_PAD]
    unsigned* Wu = (unsigned*)Ws;
    unsigned* Au = (unsigned*)As;

    int tid = threadIdx.x;
    int lane = tid & 31, wid = tid >> 5;
    int wm = wid & 3, wn = wid >> 2;
    int g = lane >> 2, t = lane & 3;
    int row0 = blockIdx.x * BM;

    {
        int r = tid >> 5, c = lane * 4;
#pragma unroll
        for (int p = 0; p < 16; p++) {
            int row = r + p * 8;
            float4 v = *(const float4*)&W[row * DD + c];
            uint4 u = make_uint4(f2tf(v.x), f2tf(v.y), f2tf(v.z), f2tf(v.w));
            *(uint4*)&Wu[row * W_PAD + c] = u;
        }
    }

    float acc[2][8][4];
#pragma unroll
    for (int mi = 0; mi < 2; mi++)
#pragma unroll
        for (int ni = 0; ni < 8; ni++)
#pragma unroll
            for (int q = 0; q < 4; q++) acc[mi][ni][q] = 0.f;

    for (int ko = 0; ko < 4; ko++) {
        __syncthreads();
        {
            int r = tid >> 3, c = (tid & 7) * 4;
#pragma unroll
            for (int p = 0; p < 4; p++) {
                int rr = r + p * 32;
                int row = row0 + rr;
                float4 v = make_float4(0.f, 0.f, 0.f, 0.f);
                if (row < NN) {
                    int off = row * DD + ko * 32 + c;
                    if (MODE == 1) {
                        v = *(const float4*)&g_agg[off];
                    } else {
                        float4 z = *(const float4*)&g_z[off];
                        float4 sc = *(const float4*)&g_scale[ko * 32 + c];
                        float4 sh = *(const float4*)&g_shift[ko * 32 + c];
                        v.x = fmaxf(fmaf(z.x, sc.x, sh.x), 0.f);
                        v.y = fmaxf(fmaf(z.y, sc.y, sh.y), 0.f);
                        v.z = fmaxf(fmaf(z.z, sc.z, sh.z), 0.f);
                        v.w = fmaxf(fmaf(z.w, sc.w, sh.w), 0.f);
                    }
                }
                uint4 u = make_uint4(f2tf(v.x), f2tf(v.y), f2tf(v.z), f2tf(v.w));
                *(uint4*)&Au[rr * A_PAD + c] = u;
            }
        }
        __syncthreads();
#pragma unroll
        for (int kk = 0; kk < 4; kk++) {
            int kb = kk * 8;
            int kw = ko * 32 + kb;
            unsigned b0[8], b1[8];
#pragma unroll
            for (int ni = 0; ni < 8; ni++) {
                int col = wn * 64 + ni * 8 + g;
                b0[ni] = Wu[(kw + t) * W_PAD + col];
                b1[ni] = Wu[(kw + t + 4) * W_PAD + col];
            }
#pragma unroll
            for (int mi = 0; mi < 2; mi++) {
                int rb = wm * 32 + mi * 16;
                unsigned a0 = Au[(rb + g) * A_PAD + kb + t];
                unsigned a1 = Au[(rb + g + 8) * A_PAD + kb + t];
                unsigned a2 = Au[(rb + g) * A_PAD + kb + t + 4];
                unsigned a3 = Au[(rb + g + 8) * A_PAD + kb + t + 4];
#pragma unroll
                for (int ni = 0; ni < 8; ni++)
                    mma8(acc[mi][ni], a0, a1, a2, a3, b0[ni], b1[ni]);
            }
        }
    }

    float bcol[16];
#pragma unroll
    for (int ni = 0; ni < 8; ni++) {
        int col = wn * 64 + ni * 8 + 2 * t;
        bcol[ni * 2]     = __ldg(&bias[col]);
        bcol[ni * 2 + 1] = __ldg(&bias[col + 1]);
    }

    if (MODE == 1) {
        float psum[16], psq[16];
#pragma unroll
        for (int i = 0; i < 16; i++) { psum[i] = 0.f; psq[i] = 0.f; }
#pragma unroll
        for (int mi = 0; mi < 2; mi++) {
            int r1 = row0 + wm * 32 + mi * 16 + g;
            int r2 = r1 + 8;
#pragma unroll
            for (int ni = 0; ni < 8; ni++) {
                int col = wn * 64 + ni * 8 + 2 * t;
                float x0 = acc[mi][ni][0] + bcol[ni * 2];
                float x1 = acc[mi][ni][1] + bcol[ni * 2 + 1];
                float x2 = acc[mi][ni][2] + bcol[ni * 2];
                float x3 = acc[mi][ni][3] + bcol[ni * 2 + 1];
                if (r1 < NN) {
                    *(float2*)&g_z[r1 * DD + col] = make_float2(x0, x1);
                    psum[ni * 2] += x0;     psq[ni * 2] += x0 * x0;
                    psum[ni * 2 + 1] += x1; psq[ni * 2 + 1] += x1 * x1;
                }
                if (r2 < NN) {
                    *(float2*)&g_z[r2 * DD + col] = make_float2(x2, x3);
                    psum[ni * 2] += x2;     psq[ni * 2] += x2 * x2;
                    psum[ni * 2 + 1] += x3; psq[ni * 2 + 1] += x3 * x3;
                }
            }
        }
#pragma unroll
        for (int d = 4; d < 32; d <<= 1) {
#pragma unroll
            for (int i = 0; i < 16; i++) {
                psum[i] += __shfl_down_sync(0xFFFFFFFFu, psum[i], d);
                psq[i]  += __shfl_down_sync(0xFFFFFFFFu, psq[i], d);
            }
        }
        __syncthreads();
        float* ssum = As;
        float* ssq  = As + DD;
        if (tid < DD) { ssum[tid] = 0.f; ssq[tid] = 0.f; }
        __syncthreads();
        if (lane < 4) {
#pragma unroll
            for (int i = 0; i < 16; i++) {
                int col = wn * 64 + (i >> 1) * 8 + 2 * t + (i & 1);
                atomicAdd(&ssum[col], psum[i]);
                atomicAdd(&ssq[col],  psq[i]);
            }
        }
        __syncthreads();
        if (tid < DD) {
            atomicAdd(&g_sum[tid],   ssum[tid]);
            atomicAdd(&g_sumsq[tid], ssq[tid]);
        }
    } else {
#pragma unroll
        for (int mi = 0; mi < 2; mi++) {
            int r1 = row0 + wm * 32 + mi * 16 + g;
            int r2 = r1 + 8;
#pragma unroll
            for (int ni = 0; ni < 8; ni++) {
                int col = wn * 64 + ni * 8 + 2 * t;
                float x0 = fmaxf(acc[mi][ni][0] + bcol[ni * 2], 0.f);
                float x1 = fmaxf(acc[mi][ni][1] + bcol[ni * 2 + 1], 0.f);
                float x2 = fmaxf(acc[mi][ni][2] + bcol[ni * 2], 0.f);
                float x3 = fmaxf(acc[mi][ni][3] + bcol[ni * 2 + 1], 0.f);
                if (r1 < NN) {
                    if (add_res) {
                        float2 rv = *(const float2*)&aux[r1 * DD + col];
                        x0 += rv.x; x1 += rv.y;
                    }
                    *(float2*)&outp[r1 * DD + col] = make_float2(x0, x1);
                }
                if (r2 < NN) {
                    if (add_res) {
                        float2 rv = *(const float2*)&aux[r2 * DD + col];
                        x2 += rv.x; x3 += rv.y;
                    }
                    *(float2*)&outp[r2 * DD + col] = make_float2(x2, x3);
                }
            }
        }
    }
}

// ---------------------------------------------------------------------------
__global__ void finalize_kernel(const float* __restrict__ gamma,
                                const float* __restrict__ beta) {
    int tt = threadIdx.x;
    if (tt < DD) {
        float mu = g_sum[tt] * (1.0f / NN);
        float var = g_sumsq[tt] * (1.0f / NN) - mu * mu;
        float rs = rsqrtf(var + 1e-5f);
        float sc = rs * gamma[tt];
        g_scale[tt] = sc;
        g_shift[tt] = beta[tt] - mu * sc;
    }
}

// ---------------------------------------------------------------------------
extern "C" void kernel_launch(void* const* d_in, const int* in_sizes, int n_in,
                              void* d_out, int out_size) {
    const float* x     = (const float*)d_in[0];
    const void*  ei    = d_in[1];
    const float* ea    = (const float*)d_in[2];
    const float* We    = (const float*)d_in[3];
    const float* be    = (const float*)d_in[4];
    const float* eps   = (const float*)d_in[5];
    const float* W1    = (const float*)d_in[6];
    const float* b1    = (const float*)d_in[7];
    const float* gamma = (const float*)d_in[8];
    const float* beta  = (const float*)d_in[9];
    const float* W2    = (const float*)d_in[10];
    const float* b2    = (const float*)d_in[11];

    void* hp;
    cudaGetSymbolAddress(&hp, g_h);
    float* gh = (float*)hp;

    cudaFuncSetAttribute(gemm_tc<1>, cudaFuncAttributeMaxDynamicSharedMemorySize, GSMEM);
    cudaFuncSetAttribute(gemm_tc<2>, cudaFuncAttributeMaxDynamicSharedMemorySize, GSMEM);

    // edge-index conversion + CSR build (per launch; graph is static input)
    detect_kernel<<<1, 1>>>((const int*)ei);
    convert_kernel<<<(NE + 255) / 256, 256>>>(ei);
    zcnt_kernel<<<NBLK, 256>>>();
    hist_kernel<<<(NE + 255) / 256, 256>>>();
    scan_block_kernel<<<NBLK, 256>>>();
    scan_part_kernel<<<1, 512>>>();
    scan_add_kernel<<<NBLK, 256>>>();
    fill_kernel<<<(NE + 255) / 256, 256>>>(ea);

    for (int l = 0; l < LL; l++) {
        const float* h_in = (l == 0) ? x : gh;
        float* h_out = (l == LL - 1) ? (float*)d_out : gh;
        gather_kernel<<<(NN * 32) / 256, 256>>>(h_in, We + l * DD, be + l * DD,
                                                eps + l);
        gemm_tc<1><<<MB, 256, GSMEM>>>(W1 + l * DD * DD, b1 + l * DD,
                                       nullptr, nullptr, 0);
        finalize_kernel<<<1, 128>>>(gamma + l * DD, beta + l * DD);
        gemm_tc<2><<<MB, 256, GSMEM>>>(W2 + l * DD * DD, b2 + l * DD,
                                       h_in, h_out, l > 0 ? 1 : 0);
    }
}